// round 4
// baseline (speedup 1.0000x reference)
#include <cuda_runtime.h>
#include <cuda_bf16.h>

// Problem constants (fixed by the reference)
#define BATCH   2
#define SEQ     2048
#define DMODEL  768
#define NHEAD   12
#define DHEAD   64
#define MROWS   (BATCH * SEQ)        // 4096
#define OUT0    ((long)MROWS * DMODEL)          // 3,145,728  (output elems)
#define ATTNSZ  ((long)BATCH * NHEAD * SEQ * SEQ) // 100,663,296 (attn elems)

// ---------------------------------------------------------------------------
// Scratch (static __device__ arrays: allocation-free per harness rules)
// ---------------------------------------------------------------------------
__device__ float g_q[BATCH * NHEAD * SEQ * DHEAD];     // head-major Q
__device__ float g_k[BATCH * NHEAD * SEQ * DHEAD];     // head-major K
__device__ float g_v[BATCH * NHEAD * SEQ * DHEAD];     // head-major V
__device__ float g_ctx[MROWS * DMODEL];                // merged context [B,S,768]
__device__ float g_attn[BATCH * NHEAD * SEQ * SEQ];    // fallback attn buffer

// ---------------------------------------------------------------------------
// Generic NT GEMM:  C[m,n] = alpha * sum_k A[m,k]*B[n,k]  (+ bias[n])
// Both A and B are row-major with K contiguous (torch Linear / QK^T pattern).
// 128x128 tile, BK=8, 256 threads, 8x8 microtile, float4 transposed smem loads.
// HEADMAJOR: write C into [b, h=n/64, s, d=n%64] layout (S=2048, H=12, Dh=64).
// Batched via blockIdx.z with element strides sA/sB/sC.
// ---------------------------------------------------------------------------
template<bool HEADMAJOR>
__global__ __launch_bounds__(256)
void gemm_nt(const float* __restrict__ A, long sA,
             const float* __restrict__ Bm, long sB,
             const float* __restrict__ bias,
             float* __restrict__ C, long sC,
             int M, int N, int K, float alpha)
{
    __shared__ float As[8][128];
    __shared__ float Bs[8][128];

    const int bz = blockIdx.z;
    A  += (long)bz * sA;
    Bm += (long)bz * sB;
    C  += (long)bz * sC;

    const int bm = blockIdx.y * 128;
    const int bn = blockIdx.x * 128;
    const int t  = threadIdx.x;

    // load mapping: 128 rows x 8 cols = 256 float4
    const int lrow = t >> 1;        // 0..127
    const int lcol = (t & 1) * 4;   // 0 or 4
    // compute mapping: 16x16 threads, 8x8 microtile
    const int tx = t & 15;
    const int ty = t >> 4;

    const float* Aptr = A  + (long)(bm + lrow) * K + lcol;
    const float* Bptr = Bm + (long)(bn + lrow) * K + lcol;

    float acc[8][8];
    #pragma unroll
    for (int i = 0; i < 8; i++)
        #pragma unroll
        for (int j = 0; j < 8; j++) acc[i][j] = 0.0f;

    for (int k0 = 0; k0 < K; k0 += 8) {
        float4 av = *reinterpret_cast<const float4*>(Aptr + k0);
        float4 bv = *reinterpret_cast<const float4*>(Bptr + k0);
        __syncthreads();
        As[lcol + 0][lrow] = av.x; As[lcol + 1][lrow] = av.y;
        As[lcol + 2][lrow] = av.z; As[lcol + 3][lrow] = av.w;
        Bs[lcol + 0][lrow] = bv.x; Bs[lcol + 1][lrow] = bv.y;
        Bs[lcol + 2][lrow] = bv.z; Bs[lcol + 3][lrow] = bv.w;
        __syncthreads();

        #pragma unroll
        for (int kk = 0; kk < 8; kk++) {
            float a[8], b[8];
            *reinterpret_cast<float4*>(&a[0]) = *reinterpret_cast<const float4*>(&As[kk][ty * 8]);
            *reinterpret_cast<float4*>(&a[4]) = *reinterpret_cast<const float4*>(&As[kk][ty * 8 + 4]);
            *reinterpret_cast<float4*>(&b[0]) = *reinterpret_cast<const float4*>(&Bs[kk][tx * 8]);
            *reinterpret_cast<float4*>(&b[4]) = *reinterpret_cast<const float4*>(&Bs[kk][tx * 8 + 4]);
            #pragma unroll
            for (int i = 0; i < 8; i++)
                #pragma unroll
                for (int j = 0; j < 8; j++)
                    acc[i][j] = fmaf(a[i], b[j], acc[i][j]);
        }
    }

    float bv8[8];
    #pragma unroll
    for (int j = 0; j < 8; j++)
        bv8[j] = bias ? bias[bn + tx * 8 + j] : 0.0f;

    #pragma unroll
    for (int i = 0; i < 8; i++) {
        const int m = bm + ty * 8 + i;
        if (HEADMAJOR) {
            const int bb = m >> 11;       // m / 2048
            const int s  = m & 2047;
            #pragma unroll
            for (int j0 = 0; j0 < 8; j0 += 4) {
                const int n = bn + tx * 8 + j0;
                const int h = n >> 6;
                const int d = n & 63;
                float4 v;
                v.x = acc[i][j0 + 0] * alpha + bv8[j0 + 0];
                v.y = acc[i][j0 + 1] * alpha + bv8[j0 + 1];
                v.z = acc[i][j0 + 2] * alpha + bv8[j0 + 2];
                v.w = acc[i][j0 + 3] * alpha + bv8[j0 + 3];
                *reinterpret_cast<float4*>(
                    &C[((long)(bb * NHEAD + h) * SEQ + s) * DHEAD + d]) = v;
            }
        } else {
            #pragma unroll
            for (int j0 = 0; j0 < 8; j0 += 4) {
                const int n = bn + tx * 8 + j0;
                float4 v;
                v.x = acc[i][j0 + 0] * alpha + bv8[j0 + 0];
                v.y = acc[i][j0 + 1] * alpha + bv8[j0 + 1];
                v.z = acc[i][j0 + 2] * alpha + bv8[j0 + 2];
                v.w = acc[i][j0 + 3] * alpha + bv8[j0 + 3];
                *reinterpret_cast<float4*>(&C[(long)m * N + n]) = v;
            }
        }
    }
}

// ---------------------------------------------------------------------------
// Row softmax in place: one block per row of 2048 floats.
// ---------------------------------------------------------------------------
__global__ __launch_bounds__(256)
void softmax_rows(float* __restrict__ attn)
{
    __shared__ float red[256];
    const long row = blockIdx.x;
    float* p = attn + row * (long)SEQ;
    const int t = threadIdx.x;

    float v[8];
    float mx = -3.0e38f;
    #pragma unroll
    for (int i = 0; i < 8; i++) {
        v[i] = p[i * 256 + t];
        mx = fmaxf(mx, v[i]);
    }
    red[t] = mx;
    __syncthreads();
    #pragma unroll
    for (int s = 128; s > 0; s >>= 1) {
        if (t < s) red[t] = fmaxf(red[t], red[t + s]);
        __syncthreads();
    }
    mx = red[0];
    __syncthreads();

    float sum = 0.0f;
    #pragma unroll
    for (int i = 0; i < 8; i++) {
        v[i] = __expf(v[i] - mx);
        sum += v[i];
    }
    red[t] = sum;
    __syncthreads();
    #pragma unroll
    for (int s = 128; s > 0; s >>= 1) {
        if (t < s) red[t] += red[t + s];
        __syncthreads();
    }
    const float inv = 1.0f / red[0];
    #pragma unroll
    for (int i = 0; i < 8; i++)
        p[i * 256 + t] = v[i] * inv;
}

// ---------------------------------------------------------------------------
// Context GEMM: ctx[b,s, h*64+d] = sum_j attn[bh, m, j] * V[bh, j, d]
// Per block: 128 queries x 64 (full Dh), K tiled by 32. 256 threads, 8x4 tile.
// Writes merged [B, S, 768] row-major so the O-projection is a plain NT GEMM.
// ---------------------------------------------------------------------------
__global__ __launch_bounds__(256)
void context_kernel(const float* __restrict__ attn,
                    const float* __restrict__ V,
                    float* __restrict__ ctx)
{
    __shared__ float As[32][128];   // [j][m], transposed
    __shared__ float Bs[32][64];    // [j][d]

    const int bh = blockIdx.y;            // b*12 + h
    const int bm = blockIdx.x * 128;
    const int b  = bh / NHEAD;
    const int h  = bh % NHEAD;

    const float* Ab = attn + (long)bh * SEQ * SEQ;
    const float* Vb = V    + (long)bh * SEQ * DHEAD;

    const int t  = threadIdx.x;
    const int tx = t & 15;   // col group: d = tx*4
    const int ty = t >> 4;   // row group: m = ty*8

    // A load mapping: 128 rows x 32 cols -> 4 float4 per thread
    const int arow = t >> 3;          // 0..31
    const int acol = (t & 7) * 4;     // 0..28
    // B load mapping: 32 rows x 64 cols -> 2 float4 per thread
    const int brow = t >> 4;          // 0..15
    const int bcol = (t & 15) * 4;    // 0..60

    float acc[8][4];
    #pragma unroll
    for (int i = 0; i < 8; i++)
        #pragma unroll
        for (int j = 0; j < 4; j++) acc[i][j] = 0.0f;

    for (int j0 = 0; j0 < SEQ; j0 += 32) {
        float4 a4[4], b4[2];
        #pragma unroll
        for (int r = 0; r < 4; r++)
            a4[r] = *reinterpret_cast<const float4*>(
                Ab + (long)(bm + arow + r * 32) * SEQ + j0 + acol);
        #pragma unroll
        for (int r = 0; r < 2; r++)
            b4[r] = *reinterpret_cast<const float4*>(
                Vb + (long)(j0 + brow + r * 16) * DHEAD + bcol);

        __syncthreads();
        #pragma unroll
        for (int r = 0; r < 4; r++) {
            As[acol + 0][arow + r * 32] = a4[r].x;
            As[acol + 1][arow + r * 32] = a4[r].y;
            As[acol + 2][arow + r * 32] = a4[r].z;
            As[acol + 3][arow + r * 32] = a4[r].w;
        }
        #pragma unroll
        for (int r = 0; r < 2; r++)
            *reinterpret_cast<float4*>(&Bs[brow + r * 16][bcol]) = b4[r];
        __syncthreads();

        #pragma unroll
        for (int jj = 0; jj < 32; jj++) {
            float a[8];
            *reinterpret_cast<float4*>(&a[0]) = *reinterpret_cast<const float4*>(&As[jj][ty * 8]);
            *reinterpret_cast<float4*>(&a[4]) = *reinterpret_cast<const float4*>(&As[jj][ty * 8 + 4]);
            float4 bv = *reinterpret_cast<const float4*>(&Bs[jj][tx * 4]);
            #pragma unroll
            for (int i = 0; i < 8; i++) {
                acc[i][0] = fmaf(a[i], bv.x, acc[i][0]);
                acc[i][1] = fmaf(a[i], bv.y, acc[i][1]);
                acc[i][2] = fmaf(a[i], bv.z, acc[i][2]);
                acc[i][3] = fmaf(a[i], bv.w, acc[i][3]);
            }
        }
    }

    #pragma unroll
    for (int i = 0; i < 8; i++) {
        const int m = bm + ty * 8 + i;
        float4 v;
        v.x = acc[i][0]; v.y = acc[i][1]; v.z = acc[i][2]; v.w = acc[i][3];
        *reinterpret_cast<float4*>(
            &ctx[((long)(b * SEQ + m)) * DMODEL + h * DHEAD + tx * 4]) = v;
    }
}

// ---------------------------------------------------------------------------
// Host launcher
// ---------------------------------------------------------------------------
extern "C" void kernel_launch(void* const* d_in, const int* in_sizes, int n_in,
                              void* d_out_, int out_size)
{
    const float* q    = (const float*)d_in[0];
    const float* k    = (const float*)d_in[1];
    const float* v    = (const float*)d_in[2];
    const float* wq_w = (const float*)d_in[3];
    const float* wq_b = (const float*)d_in[4];
    const float* wk_w = (const float*)d_in[5];
    const float* wk_b = (const float*)d_in[6];
    const float* wv_w = (const float*)d_in[7];
    const float* wv_b = (const float*)d_in[8];
    const float* wo_w = (const float*)d_in[9];
    const float* wo_b = (const float*)d_in[10];
    float* d_out = (float*)d_out_;

    float *gq, *gk, *gv, *gctx, *gattn;
    { void* p;
      cudaGetSymbolAddress(&p, g_q);    gq    = (float*)p;
      cudaGetSymbolAddress(&p, g_k);    gk    = (float*)p;
      cudaGetSymbolAddress(&p, g_v);    gv    = (float*)p;
      cudaGetSymbolAddress(&p, g_ctx);  gctx  = (float*)p;
      cudaGetSymbolAddress(&p, g_attn); gattn = (float*)p;
    }

    // Output layout handling (reference returns (output, attn_weights))
    float* attnp;
    bool do_output = true;
    if ((long)out_size >= OUT0 + ATTNSZ) {
        attnp = d_out + OUT0;                 // both outputs in d_out
    } else if ((long)out_size >= OUT0) {
        attnp = gattn;                        // only 'output' requested
    } else {
        attnp = d_out;                        // only attn requested
        do_output = false;
    }

    const dim3 blk(256);
    const long sQKV = (long)SEQ * DHEAD;      // per-(b,h) stride

    // 1-3. Q/K/V projections -> head-major
    gemm_nt<true><<<dim3(DMODEL / 128, MROWS / 128, 1), blk>>>(
        q, 0, wq_w, 0, wq_b, gq, 0, MROWS, DMODEL, DMODEL, 1.0f);
    gemm_nt<true><<<dim3(DMODEL / 128, MROWS / 128, 1), blk>>>(
        k, 0, wk_w, 0, wk_b, gk, 0, MROWS, DMODEL, DMODEL, 1.0f);
    gemm_nt<true><<<dim3(DMODEL / 128, MROWS / 128, 1), blk>>>(
        v, 0, wv_w, 0, wv_b, gv, 0, MROWS, DMODEL, DMODEL, 1.0f);

    // 4. Scores: batched NT GEMM over bh, alpha = 1/sqrt(64)
    gemm_nt<false><<<dim3(SEQ / 128, SEQ / 128, BATCH * NHEAD), blk>>>(
        gq, sQKV, gk, sQKV, nullptr, attnp, (long)SEQ * SEQ,
        SEQ, SEQ, DHEAD, 0.125f);

    // 5. Softmax in place -> attn_weights
    softmax_rows<<<BATCH * NHEAD * SEQ, 256>>>(attnp);

    if (do_output) {
        // 6. Context = attn @ V, merged [B,S,768]
        context_kernel<<<dim3(SEQ / 128, BATCH * NHEAD), blk>>>(attnp, gv, gctx);

        // 7. Output projection -> d_out[0 : OUT0]
        gemm_nt<false><<<dim3(DMODEL / 128, MROWS / 128, 1), blk>>>(
            gctx, 0, wo_w, 0, wo_b, d_out, 0, MROWS, DMODEL, DMODEL, 1.0f);
    }
}

// round 7
// speedup vs baseline: 1.5965x; 1.5965x over previous
#include <cuda_runtime.h>
#include <cuda_bf16.h>

// Problem constants (fixed by the reference)
#define BATCH   2
#define SEQ     2048
#define DMODEL  768
#define NHEAD   12
#define DHEAD   64
#define MROWS   (BATCH * SEQ)                      // 4096
#define OUT0    ((long)MROWS * DMODEL)             // 3,145,728
#define ATTNSZ  ((long)BATCH * NHEAD * SEQ * SEQ)  // 100,663,296

// ---------------------------------------------------------------------------
// Scratch (static __device__ arrays: allocation-free per harness rules)
// ---------------------------------------------------------------------------
__device__ float g_q[BATCH * NHEAD * SEQ * DHEAD];     // head-major Q
__device__ float g_k[BATCH * NHEAD * SEQ * DHEAD];     // head-major K
__device__ float g_v[BATCH * NHEAD * SEQ * DHEAD];     // head-major V
__device__ float g_ctx[MROWS * DMODEL];                // merged context [B,S,768]
__device__ float g_attn[BATCH * NHEAD * SEQ * SEQ];    // fallback attn buffer

__device__ __forceinline__ unsigned f2tf32(float f) {
    unsigned u;
    asm("cvt.rna.tf32.f32 %0, %1;" : "=r"(u) : "f"(f));
    return u;
}

__device__ __forceinline__ void mma_tf32(float c[4], const unsigned a[4], const unsigned b[2]) {
    asm volatile(
        "mma.sync.aligned.m16n8k8.row.col.f32.tf32.tf32.f32 "
        "{%0,%1,%2,%3}, {%4,%5,%6,%7}, {%8,%9}, {%0,%1,%2,%3};\n"
        : "+f"(c[0]), "+f"(c[1]), "+f"(c[2]), "+f"(c[3])
        : "r"(a[0]), "r"(a[1]), "r"(a[2]), "r"(a[3]), "r"(b[0]), "r"(b[1]));
}

// ---------------------------------------------------------------------------
// Generic tf32 tensor-core GEMM.
//   C[m,n] = alpha * sum_k A[m,k] * Bop[k,n]  (+ bias[n])
// BT=true : B given as N x K row-major (NT GEMM: torch Linear / QK^T).
// BT=false: B given as K x N row-major (NN GEMM: attn @ V).
// MODE: 0 = plain row-major C (N stride), batched via sC
//       1 = head-major write [b, h=n/64, s=m%2048, d=n%64]   (projections)
//       2 = merged-context write ctx[b*S + m][h*64 + n], bz = b*12+h
// Block: BM=128 x BN, BK=32, 256 threads (8 warps), warp tile WMx32,
// mma.sync.m16n8k8 tf32, fp32 accumulate.
// ---------------------------------------------------------------------------
template<int BN, bool BT, int MODE>
__global__ __launch_bounds__(256)
void gemm_tf32(const float* __restrict__ A, long sA,
               const float* __restrict__ B, long sB,
               const float* __restrict__ bias,
               float* __restrict__ C, long sC,
               int M, int N, int K, float alpha)
{
    constexpr int BM = 128, BK = 32;
    constexpr int WARPS_N = (BN == 128) ? 4 : 2;
    constexpr int WARPS_M = 8 / WARPS_N;
    constexpr int WM = BM / WARPS_M;     // 64 or 32... (64 for BN=128)
    constexpr int WN = BN / WARPS_N;     // 32
    constexpr int MI = WM / 16;          // 4 or 2
    constexpr int NJ = WN / 8;           // 4
    constexpr int BLOADS = BN * BK / 1024;  // float4 loads of B per thread

    __shared__ unsigned As[BK][BM + 4];
    __shared__ unsigned Bs[BK][BN + 4];

    const int bz = blockIdx.z;
    A += (long)bz * sA;
    B += (long)bz * sB;
    C += (long)bz * sC;

    const int bm = blockIdx.y * BM;
    const int bn = blockIdx.x * BN;
    const int t    = threadIdx.x;
    const int warp = t >> 5;
    const int lane = t & 31;
    const int g    = lane >> 2;   // group id 0..7
    const int tig  = lane & 3;    // thread-in-group 0..3
    const int wm = (warp / WARPS_N) * WM;
    const int wn = (warp % WARPS_N) * WN;

    float acc[MI][NJ][4];
    #pragma unroll
    for (int i = 0; i < MI; i++)
        #pragma unroll
        for (int j = 0; j < NJ; j++)
            #pragma unroll
            for (int r = 0; r < 4; r++) acc[i][j][r] = 0.0f;

    // A load mapping: 128 rows x 32 k -> 4 float4/thread
    const int arow = t >> 3;        // 0..31
    const int ak   = (t & 7) * 4;   // k offset 0..28
    // B NN load mapping: BK x BN tile
    const int brow = t / (BN / 4);          // rows per pass = 1024/BN
    const int bcol = (t % (BN / 4)) * 4;
    constexpr int BROWS = 1024 / BN;        // rows covered per pass

    for (int k0 = 0; k0 < K; k0 += BK) {
        float4 a4[4];
        #pragma unroll
        for (int r = 0; r < 4; r++)
            a4[r] = *reinterpret_cast<const float4*>(
                &A[(long)(bm + arow + 32 * r) * K + k0 + ak]);

        float4 b4[BLOADS];
        if (BT) {
            #pragma unroll
            for (int r = 0; r < BLOADS; r++)
                b4[r] = *reinterpret_cast<const float4*>(
                    &B[(long)(bn + arow + 32 * r) * K + k0 + ak]);
        } else {
            #pragma unroll
            for (int r = 0; r < BLOADS; r++)
                b4[r] = *reinterpret_cast<const float4*>(
                    &B[(long)(k0 + brow + BROWS * r) * N + bn + bcol]);
        }

        __syncthreads();
        #pragma unroll
        for (int r = 0; r < 4; r++) {
            As[ak + 0][arow + 32 * r] = f2tf32(a4[r].x);
            As[ak + 1][arow + 32 * r] = f2tf32(a4[r].y);
            As[ak + 2][arow + 32 * r] = f2tf32(a4[r].z);
            As[ak + 3][arow + 32 * r] = f2tf32(a4[r].w);
        }
        if (BT) {
            #pragma unroll
            for (int r = 0; r < BLOADS; r++) {
                Bs[ak + 0][arow + 32 * r] = f2tf32(b4[r].x);
                Bs[ak + 1][arow + 32 * r] = f2tf32(b4[r].y);
                Bs[ak + 2][arow + 32 * r] = f2tf32(b4[r].z);
                Bs[ak + 3][arow + 32 * r] = f2tf32(b4[r].w);
            }
        } else {
            #pragma unroll
            for (int r = 0; r < BLOADS; r++) {
                Bs[brow + BROWS * r][bcol + 0] = f2tf32(b4[r].x);
                Bs[brow + BROWS * r][bcol + 1] = f2tf32(b4[r].y);
                Bs[brow + BROWS * r][bcol + 2] = f2tf32(b4[r].z);
                Bs[brow + BROWS * r][bcol + 3] = f2tf32(b4[r].w);
            }
        }
        __syncthreads();

        #pragma unroll
        for (int ks = 0; ks < BK / 8; ks++) {
            unsigned af[MI][4], bf[NJ][2];
            #pragma unroll
            for (int mi = 0; mi < MI; mi++) {
                const int mrow = wm + mi * 16 + g;
                af[mi][0] = As[ks * 8 + tig    ][mrow    ];
                af[mi][1] = As[ks * 8 + tig    ][mrow + 8];
                af[mi][2] = As[ks * 8 + tig + 4][mrow    ];
                af[mi][3] = As[ks * 8 + tig + 4][mrow + 8];
            }
            #pragma unroll
            for (int nj = 0; nj < NJ; nj++) {
                const int ncol = wn + nj * 8 + g;
                bf[nj][0] = Bs[ks * 8 + tig    ][ncol];
                bf[nj][1] = Bs[ks * 8 + tig + 4][ncol];
            }
            #pragma unroll
            for (int mi = 0; mi < MI; mi++)
                #pragma unroll
                for (int nj = 0; nj < NJ; nj++)
                    mma_tf32(acc[mi][nj], af[mi], bf[nj]);
        }
    }

    // Epilogue
    #pragma unroll
    for (int mi = 0; mi < MI; mi++) {
        #pragma unroll
        for (int nj = 0; nj < NJ; nj++) {
            const int m0 = bm + wm + mi * 16 + g;
            const int n0 = bn + wn + nj * 8 + tig * 2;
            float bv0 = bias ? bias[n0]     : 0.0f;
            float bv1 = bias ? bias[n0 + 1] : 0.0f;
            float2 v0, v1;
            v0.x = acc[mi][nj][0] * alpha + bv0;
            v0.y = acc[mi][nj][1] * alpha + bv1;
            v1.x = acc[mi][nj][2] * alpha + bv0;
            v1.y = acc[mi][nj][3] * alpha + bv1;

            if (MODE == 1) {
                const int h = n0 >> 6, d = n0 & 63;
                const int b0i = m0 >> 11,       s0 = m0 & 2047;
                const int b1i = (m0 + 8) >> 11, s1 = (m0 + 8) & 2047;
                *reinterpret_cast<float2*>(
                    &C[((long)(b0i * NHEAD + h) * SEQ + s0) * DHEAD + d]) = v0;
                *reinterpret_cast<float2*>(
                    &C[((long)(b1i * NHEAD + h) * SEQ + s1) * DHEAD + d]) = v1;
            } else if (MODE == 2) {
                const int b = bz / NHEAD, h = bz % NHEAD;
                *reinterpret_cast<float2*>(
                    &C[((long)(b * SEQ + m0)) * DMODEL + h * DHEAD + n0]) = v0;
                *reinterpret_cast<float2*>(
                    &C[((long)(b * SEQ + m0 + 8)) * DMODEL + h * DHEAD + n0]) = v1;
            } else {
                *reinterpret_cast<float2*>(&C[(long)m0 * N + n0]) = v0;
                *reinterpret_cast<float2*>(&C[(long)(m0 + 8) * N + n0]) = v1;
            }
        }
    }
}

// ---------------------------------------------------------------------------
// Row softmax in place: one block per row of 2048 floats.
// ---------------------------------------------------------------------------
__global__ __launch_bounds__(256)
void softmax_rows(float* __restrict__ attn)
{
    __shared__ float red[256];
    const long row = blockIdx.x;
    float* p = attn + row * (long)SEQ;
    const int t = threadIdx.x;

    float v[8];
    float mx = -3.0e38f;
    #pragma unroll
    for (int i = 0; i < 8; i++) {
        v[i] = p[i * 256 + t];
        mx = fmaxf(mx, v[i]);
    }
    red[t] = mx;
    __syncthreads();
    #pragma unroll
    for (int s = 128; s > 0; s >>= 1) {
        if (t < s) red[t] = fmaxf(red[t], red[t + s]);
        __syncthreads();
    }
    mx = red[0];
    __syncthreads();

    float sum = 0.0f;
    #pragma unroll
    for (int i = 0; i < 8; i++) {
        v[i] = __expf(v[i] - mx);
        sum += v[i];
    }
    red[t] = sum;
    __syncthreads();
    #pragma unroll
    for (int s = 128; s > 0; s >>= 1) {
        if (t < s) red[t] += red[t + s];
        __syncthreads();
    }
    const float inv = 1.0f / red[0];
    #pragma unroll
    for (int i = 0; i < 8; i++)
        p[i * 256 + t] = v[i] * inv;
}

// ---------------------------------------------------------------------------
// Host launcher
// ---------------------------------------------------------------------------
extern "C" void kernel_launch(void* const* d_in, const int* in_sizes, int n_in,
                              void* d_out_, int out_size)
{
    const float* q    = (const float*)d_in[0];
    const float* k    = (const float*)d_in[1];
    const float* v    = (const float*)d_in[2];
    const float* wq_w = (const float*)d_in[3];
    const float* wq_b = (const float*)d_in[4];
    const float* wk_w = (const float*)d_in[5];
    const float* wk_b = (const float*)d_in[6];
    const float* wv_w = (const float*)d_in[7];
    const float* wv_b = (const float*)d_in[8];
    const float* wo_w = (const float*)d_in[9];
    const float* wo_b = (const float*)d_in[10];
    float* d_out = (float*)d_out_;

    float *gq, *gk, *gv, *gctx, *gattn;
    { void* p;
      cudaGetSymbolAddress(&p, g_q);    gq    = (float*)p;
      cudaGetSymbolAddress(&p, g_k);    gk    = (float*)p;
      cudaGetSymbolAddress(&p, g_v);    gv    = (float*)p;
      cudaGetSymbolAddress(&p, g_ctx);  gctx  = (float*)p;
      cudaGetSymbolAddress(&p, g_attn); gattn = (float*)p;
    }

    // Output layout handling (reference returns (output, attn_weights))
    float* attnp;
    bool do_output = true;
    if ((long)out_size >= OUT0 + ATTNSZ) {
        attnp = d_out + OUT0;                 // both outputs in d_out
    } else if ((long)out_size >= OUT0) {
        attnp = gattn;                        // only 'output' requested
    } else {
        attnp = d_out;                        // only attn requested
        do_output = false;
    }

    const dim3 blk(256);
    const long sQKV = (long)SEQ * DHEAD;      // per-(b,h) stride

    // 1-3. Q/K/V projections -> head-major  (NT, tf32 MMA)
    gemm_tf32<128, true, 1><<<dim3(DMODEL / 128, MROWS / 128, 1), blk>>>(
        q, 0, wq_w, 0, wq_b, gq, 0, MROWS, DMODEL, DMODEL, 1.0f);
    gemm_tf32<128, true, 1><<<dim3(DMODEL / 128, MROWS / 128, 1), blk>>>(
        k, 0, wk_w, 0, wk_b, gk, 0, MROWS, DMODEL, DMODEL, 1.0f);
    gemm_tf32<128, true, 1><<<dim3(DMODEL / 128, MROWS / 128, 1), blk>>>(
        v, 0, wv_w, 0, wv_b, gv, 0, MROWS, DMODEL, DMODEL, 1.0f);

    // 4. Scores: batched NT over bh, alpha = 1/sqrt(64)
    gemm_tf32<128, true, 0><<<dim3(SEQ / 128, SEQ / 128, BATCH * NHEAD), blk>>>(
        gq, sQKV, gk, sQKV, nullptr, attnp, (long)SEQ * SEQ,
        SEQ, SEQ, DHEAD, 0.125f);

    // 5. Softmax in place -> attn_weights
    softmax_rows<<<BATCH * NHEAD * SEQ, 256>>>(attnp);

    if (do_output) {
        // 6. Context = attn @ V (NN), merged write into [B,S,768]
        gemm_tf32<64, false, 2><<<dim3(1, SEQ / 128, BATCH * NHEAD), blk>>>(
            attnp, (long)SEQ * SEQ, gv, sQKV, nullptr, gctx, 0,
            SEQ, DHEAD, SEQ, 1.0f);

        // 7. Output projection -> d_out[0 : OUT0]
        gemm_tf32<128, true, 0><<<dim3(DMODEL / 128, MROWS / 128, 1), blk>>>(
            gctx, 0, wo_w, 0, wo_b, d_out, 0, MROWS, DMODEL, DMODEL, 1.0f);
    }
}

// round 10
// speedup vs baseline: 2.4426x; 1.5299x over previous
#include <cuda_runtime.h>

// Problem constants (fixed by the reference)
#define BATCH   2
#define SEQ     2048
#define DMODEL  768
#define NHEAD   12
#define DHEAD   64
#define MROWS   (BATCH * SEQ)                      // 4096
#define OUT0    ((long)MROWS * DMODEL)             // 3,145,728
#define ATTNSZ  ((long)BATCH * NHEAD * SEQ * SEQ)  // 100,663,296

// ---------------------------------------------------------------------------
// Scratch (static __device__ arrays: allocation-free per harness rules)
// ---------------------------------------------------------------------------
__device__ float g_q[BATCH * NHEAD * SEQ * DHEAD];     // head-major Q
__device__ float g_k[BATCH * NHEAD * SEQ * DHEAD];     // head-major K
__device__ float g_v[BATCH * NHEAD * SEQ * DHEAD];     // head-major V
__device__ float g_ctx[MROWS * DMODEL];                // merged context [B,S,768]
__device__ float g_attn[BATCH * NHEAD * SEQ * SEQ];    // fallback attn buffer

__device__ __forceinline__ unsigned f2tf32(float f) {
    unsigned u;
    asm("cvt.rna.tf32.f32 %0, %1;" : "=r"(u) : "f"(f));
    return u;
}

__device__ __forceinline__ void mma_tf32(float c[4], const unsigned a[4], const unsigned b[2]) {
    asm volatile(
        "mma.sync.aligned.m16n8k8.row.col.f32.tf32.tf32.f32 "
        "{%0,%1,%2,%3}, {%4,%5,%6,%7}, {%8,%9}, {%0,%1,%2,%3};\n"
        : "+f"(c[0]), "+f"(c[1]), "+f"(c[2]), "+f"(c[3])
        : "r"(a[0]), "r"(a[1]), "r"(a[2]), "r"(a[3]), "r"(b[0]), "r"(b[1]));
}

__device__ __forceinline__ uint4 cvt4(float4 v) {
    uint4 u;
    u.x = f2tf32(v.x); u.y = f2tf32(v.y); u.z = f2tf32(v.z); u.w = f2tf32(v.w);
    return u;
}

// ===========================================================================
// Projection / output GEMM (NT):  C[m,n] = sum_k A[m,k]*B[n,k] + bias[n]
// A: M x K row-major, B: N x K row-major. BM=BN=128, BK=32, 256 thr, 8 warps
// (2x4), warp tile 64x32, K-contiguous smem [m][k], global prefetch.
// MODE 1: head-major write [b, h=n/64, s=m%2048, d=n%64]. MODE 0: row-major.
// ===========================================================================
template<int MODE>
__global__ __launch_bounds__(256)
void gemm_proj(const float* __restrict__ A, const float* __restrict__ B,
               const float* __restrict__ bias, float* __restrict__ C,
               int N, int K)
{
    constexpr int BK = 32;
    __shared__ unsigned As[128][BK + 4];
    __shared__ unsigned Bs[128][BK + 4];

    const int bm = blockIdx.y * 128;
    const int bn = blockIdx.x * 128;
    const int t = threadIdx.x, warp = t >> 5, lane = t & 31;
    const int g = lane >> 2, tig = lane & 3;
    const int wm = (warp >> 2) * 64;     // 2 warps in M
    const int wn = (warp & 3) * 32;      // 4 warps in N

    const int lrow = t >> 3;             // 0..31
    const int lk   = (t & 7) * 4;        // 0..28

    float acc[4][4][4];
    #pragma unroll
    for (int i = 0; i < 4; i++)
        #pragma unroll
        for (int j = 0; j < 4; j++)
            #pragma unroll
            for (int r = 0; r < 4; r++) acc[i][j][r] = 0.0f;

    float4 a4[4], b4[4];
    #pragma unroll
    for (int r = 0; r < 4; r++) {
        a4[r] = *reinterpret_cast<const float4*>(&A[(long)(bm + lrow + 32 * r) * K + lk]);
        b4[r] = *reinterpret_cast<const float4*>(&B[(long)(bn + lrow + 32 * r) * K + lk]);
    }

    for (int k0 = 0; k0 < K; k0 += BK) {
        __syncthreads();
        #pragma unroll
        for (int r = 0; r < 4; r++) {
            *reinterpret_cast<uint4*>(&As[lrow + 32 * r][lk]) = cvt4(a4[r]);
            *reinterpret_cast<uint4*>(&Bs[lrow + 32 * r][lk]) = cvt4(b4[r]);
        }
        __syncthreads();
        if (k0 + BK < K) {
            #pragma unroll
            for (int r = 0; r < 4; r++) {
                a4[r] = *reinterpret_cast<const float4*>(
                    &A[(long)(bm + lrow + 32 * r) * K + k0 + BK + lk]);
                b4[r] = *reinterpret_cast<const float4*>(
                    &B[(long)(bn + lrow + 32 * r) * K + k0 + BK + lk]);
            }
        }

        #pragma unroll
        for (int ks = 0; ks < BK / 8; ks++) {
            const int kk = ks * 8;
            unsigned af[4][4], bf[4][2];
            #pragma unroll
            for (int mi = 0; mi < 4; mi++) {
                const int mrow = wm + mi * 16 + g;
                af[mi][0] = As[mrow    ][kk + tig    ];
                af[mi][1] = As[mrow + 8][kk + tig    ];
                af[mi][2] = As[mrow    ][kk + tig + 4];
                af[mi][3] = As[mrow + 8][kk + tig + 4];
            }
            #pragma unroll
            for (int nj = 0; nj < 4; nj++) {
                const int ncol = wn + nj * 8 + g;
                bf[nj][0] = Bs[ncol][kk + tig    ];
                bf[nj][1] = Bs[ncol][kk + tig + 4];
            }
            #pragma unroll
            for (int mi = 0; mi < 4; mi++)
                #pragma unroll
                for (int nj = 0; nj < 4; nj++)
                    mma_tf32(acc[mi][nj], af[mi], bf[nj]);
        }
    }

    #pragma unroll
    for (int mi = 0; mi < 4; mi++) {
        #pragma unroll
        for (int nj = 0; nj < 4; nj++) {
            const int m0 = bm + wm + mi * 16 + g;
            const int n0 = bn + wn + nj * 8 + tig * 2;
            const float bv0 = bias[n0], bv1 = bias[n0 + 1];
            float2 v0, v1;
            v0.x = acc[mi][nj][0] + bv0; v0.y = acc[mi][nj][1] + bv1;
            v1.x = acc[mi][nj][2] + bv0; v1.y = acc[mi][nj][3] + bv1;
            if (MODE == 1) {
                const int h = n0 >> 6, d = n0 & 63;
                const int b0i = m0 >> 11,       s0 = m0 & 2047;
                const int b1i = (m0 + 8) >> 11, s1 = (m0 + 8) & 2047;
                *reinterpret_cast<float2*>(
                    &C[((long)(b0i * NHEAD + h) * SEQ + s0) * DHEAD + d]) = v0;
                *reinterpret_cast<float2*>(
                    &C[((long)(b1i * NHEAD + h) * SEQ + s1) * DHEAD + d]) = v1;
            } else {
                *reinterpret_cast<float2*>(&C[(long)m0 * N + n0]) = v0;
                *reinterpret_cast<float2*>(&C[(long)(m0 + 8) * N + n0]) = v1;
            }
        }
    }
}

// ===========================================================================
// Scores GEMM: attn[bh, m, n] = 0.125 * sum_d Q[bh,m,d]*K[bh,n,d]
// Single BK=64 shot (whole K), dynamic smem, 128x128 tile, streaming stores.
// ===========================================================================
#define SC_SMEM_BYTES (2 * 128 * 68 * 4)

__global__ __launch_bounds__(256)
void scores_kernel(const float* __restrict__ Q, const float* __restrict__ Km,
                   float* __restrict__ attn)
{
    extern __shared__ unsigned sm[];
    unsigned (*As)[68] = reinterpret_cast<unsigned(*)[68]>(sm);
    unsigned (*Bs)[68] = reinterpret_cast<unsigned(*)[68]>(sm + 128 * 68);

    const int bh = blockIdx.z;
    const int bm = blockIdx.y * 128;
    const int bn = blockIdx.x * 128;
    const float* A = Q  + (long)bh * SEQ * DHEAD;
    const float* B = Km + (long)bh * SEQ * DHEAD;
    float* C = attn + (long)bh * SEQ * SEQ;

    const int t = threadIdx.x, warp = t >> 5, lane = t & 31;
    const int g = lane >> 2, tig = lane & 3;
    const int wm = (warp >> 2) * 64;
    const int wn = (warp & 3) * 32;

    const int lrow = t >> 4;             // 0..15
    const int lk   = (t & 15) * 4;       // 0..60

    // front-batched global loads (MLP = 16)
    float4 a4[8], b4[8];
    #pragma unroll
    for (int r = 0; r < 8; r++) {
        a4[r] = *reinterpret_cast<const float4*>(&A[(long)(bm + lrow + 16 * r) * DHEAD + lk]);
        b4[r] = *reinterpret_cast<const float4*>(&B[(long)(bn + lrow + 16 * r) * DHEAD + lk]);
    }
    #pragma unroll
    for (int r = 0; r < 8; r++) {
        *reinterpret_cast<uint4*>(&As[lrow + 16 * r][lk]) = cvt4(a4[r]);
        *reinterpret_cast<uint4*>(&Bs[lrow + 16 * r][lk]) = cvt4(b4[r]);
    }
    __syncthreads();

    float acc[4][4][4];
    #pragma unroll
    for (int i = 0; i < 4; i++)
        #pragma unroll
        for (int j = 0; j < 4; j++)
            #pragma unroll
            for (int r = 0; r < 4; r++) acc[i][j][r] = 0.0f;

    #pragma unroll
    for (int ks = 0; ks < 8; ks++) {
        const int kk = ks * 8;
        unsigned af[4][4], bf[4][2];
        #pragma unroll
        for (int mi = 0; mi < 4; mi++) {
            const int mrow = wm + mi * 16 + g;
            af[mi][0] = As[mrow    ][kk + tig    ];
            af[mi][1] = As[mrow + 8][kk + tig    ];
            af[mi][2] = As[mrow    ][kk + tig + 4];
            af[mi][3] = As[mrow + 8][kk + tig + 4];
        }
        #pragma unroll
        for (int nj = 0; nj < 4; nj++) {
            const int ncol = wn + nj * 8 + g;
            bf[nj][0] = Bs[ncol][kk + tig    ];
            bf[nj][1] = Bs[ncol][kk + tig + 4];
        }
        #pragma unroll
        for (int mi = 0; mi < 4; mi++)
            #pragma unroll
            for (int nj = 0; nj < 4; nj++)
                mma_tf32(acc[mi][nj], af[mi], bf[nj]);
    }

    #pragma unroll
    for (int mi = 0; mi < 4; mi++) {
        #pragma unroll
        for (int nj = 0; nj < 4; nj++) {
            const int m0 = bm + wm + mi * 16 + g;
            const int n0 = bn + wn + nj * 8 + tig * 2;
            float2 v0, v1;
            v0.x = acc[mi][nj][0] * 0.125f; v0.y = acc[mi][nj][1] * 0.125f;
            v1.x = acc[mi][nj][2] * 0.125f; v1.y = acc[mi][nj][3] * 0.125f;
            __stcs(reinterpret_cast<float2*>(&C[(long)m0 * SEQ + n0]), v0);
            __stcs(reinterpret_cast<float2*>(&C[(long)(m0 + 8) * SEQ + n0]), v1);
        }
    }
}

// ===========================================================================
// Fused softmax + context:
//   pass 1: per-row max & sum (warp-per-row reduction, 16 rows/warp)
//   pass 2: p = exp(s-mx)*inv -> write normalized attn (__stcs) AND
//           ctx[b,s,h*64+d] += p @ V via tf32 MMA (128x64 tile, j-tiled 32).
// One block = 128 query rows of one (b,h).
// ===========================================================================
__global__ __launch_bounds__(256)
void softmax_context(float* __restrict__ attn, const float* __restrict__ V,
                     float* __restrict__ ctx)
{
    constexpr int BK = 32;
    __shared__ unsigned Ps[128][BK + 4];
    __shared__ unsigned Vs[64][BK + 4];
    __shared__ float s_mx[128], s_inv[128];

    const int bh = blockIdx.y;
    const int b = bh / NHEAD, h = bh % NHEAD;
    const int bm = blockIdx.x * 128;
    float* Ab = attn + (long)bh * SEQ * SEQ + (long)bm * SEQ;
    const float* Vb = V + (long)bh * SEQ * DHEAD;

    const int t = threadIdx.x, warp = t >> 5, lane = t & 31;
    const int g = lane >> 2, tig = lane & 3;
    const int wm = (warp >> 1) * 32;     // 4 warps in M
    const int wn = (warp & 1) * 32;      // 2 warps in N

    // ---- pass 1: row max & sum ----
    for (int r = 0; r < 16; r++) {
        const int row = warp * 16 + r;
        const float* p = Ab + (long)row * SEQ;
        float4 v[16];
        #pragma unroll
        for (int i = 0; i < 16; i++)
            v[i] = *reinterpret_cast<const float4*>(p + i * 128 + lane * 4);
        float mx = -3.0e38f;
        #pragma unroll
        for (int i = 0; i < 16; i++) {
            mx = fmaxf(mx, fmaxf(fmaxf(v[i].x, v[i].y), fmaxf(v[i].z, v[i].w)));
        }
        #pragma unroll
        for (int o = 16; o > 0; o >>= 1)
            mx = fmaxf(mx, __shfl_xor_sync(0xFFFFFFFFu, mx, o));
        float sum = 0.0f;
        #pragma unroll
        for (int i = 0; i < 16; i++) {
            sum += __expf(v[i].x - mx) + __expf(v[i].y - mx)
                 + __expf(v[i].z - mx) + __expf(v[i].w - mx);
        }
        #pragma unroll
        for (int o = 16; o > 0; o >>= 1)
            sum += __shfl_xor_sync(0xFFFFFFFFu, sum, o);
        if (lane == 0) { s_mx[row] = mx; s_inv[row] = 1.0f / sum; }
    }
    __syncthreads();

    // ---- pass 2: normalize + write attn + context MMA ----
    const int lrow = t >> 3;             // 0..31  (P rows)
    const int lk   = (t & 7) * 4;        // 0..28  (j offset)
    const int vrow = t >> 4;             // 0..15  (V j-rows)
    const int vcol = (t & 15) * 4;       // 0..60  (V d cols)

    float acc[2][4][4];
    #pragma unroll
    for (int i = 0; i < 2; i++)
        #pragma unroll
        for (int j = 0; j < 4; j++)
            #pragma unroll
            for (int r = 0; r < 4; r++) acc[i][j][r] = 0.0f;

    float4 pa[4], pv[2];
    #pragma unroll
    for (int r = 0; r < 4; r++)
        pa[r] = *reinterpret_cast<const float4*>(&Ab[(long)(lrow + 32 * r) * SEQ + lk]);
    #pragma unroll
    for (int r = 0; r < 2; r++)
        pv[r] = *reinterpret_cast<const float4*>(&Vb[(long)(vrow + 16 * r) * DHEAD + vcol]);

    for (int j0 = 0; j0 < SEQ; j0 += BK) {
        __syncthreads();
        #pragma unroll
        for (int r = 0; r < 4; r++) {
            const int row = lrow + 32 * r;
            const float mx = s_mx[row], inv = s_inv[row];
            float4 q;
            q.x = __expf(pa[r].x - mx) * inv;
            q.y = __expf(pa[r].y - mx) * inv;
            q.z = __expf(pa[r].z - mx) * inv;
            q.w = __expf(pa[r].w - mx) * inv;
            __stcs(reinterpret_cast<float4*>(&Ab[(long)row * SEQ + j0 + lk]), q);
            *reinterpret_cast<uint4*>(&Ps[row][lk]) = cvt4(q);
        }
        #pragma unroll
        for (int r = 0; r < 2; r++) {
            Vs[vcol + 0][vrow + 16 * r] = f2tf32(pv[r].x);
            Vs[vcol + 1][vrow + 16 * r] = f2tf32(pv[r].y);
            Vs[vcol + 2][vrow + 16 * r] = f2tf32(pv[r].z);
            Vs[vcol + 3][vrow + 16 * r] = f2tf32(pv[r].w);
        }
        __syncthreads();
        if (j0 + BK < SEQ) {
            #pragma unroll
            for (int r = 0; r < 4; r++)
                pa[r] = *reinterpret_cast<const float4*>(
                    &Ab[(long)(lrow + 32 * r) * SEQ + j0 + BK + lk]);
            #pragma unroll
            for (int r = 0; r < 2; r++)
                pv[r] = *reinterpret_cast<const float4*>(
                    &Vb[(long)(j0 + BK + vrow + 16 * r) * DHEAD + vcol]);
        }

        #pragma unroll
        for (int ks = 0; ks < BK / 8; ks++) {
            const int kk = ks * 8;
            unsigned af[2][4], bf[4][2];
            #pragma unroll
            for (int mi = 0; mi < 2; mi++) {
                const int mrow = wm + mi * 16 + g;
                af[mi][0] = Ps[mrow    ][kk + tig    ];
                af[mi][1] = Ps[mrow + 8][kk + tig    ];
                af[mi][2] = Ps[mrow    ][kk + tig + 4];
                af[mi][3] = Ps[mrow + 8][kk + tig + 4];
            }
            #pragma unroll
            for (int nj = 0; nj < 4; nj++) {
                const int ncol = wn + nj * 8 + g;
                bf[nj][0] = Vs[ncol][kk + tig    ];
                bf[nj][1] = Vs[ncol][kk + tig + 4];
            }
            #pragma unroll
            for (int mi = 0; mi < 2; mi++)
                #pragma unroll
                for (int nj = 0; nj < 4; nj++)
                    mma_tf32(acc[mi][nj], af[mi], bf[nj]);
        }
    }

    #pragma unroll
    for (int mi = 0; mi < 2; mi++) {
        #pragma unroll
        for (int nj = 0; nj < 4; nj++) {
            const int m0 = bm + wm + mi * 16 + g;
            const int n0 = wn + nj * 8 + tig * 2;
            float2 v0, v1;
            v0.x = acc[mi][nj][0]; v0.y = acc[mi][nj][1];
            v1.x = acc[mi][nj][2]; v1.y = acc[mi][nj][3];
            *reinterpret_cast<float2*>(
                &ctx[((long)(b * SEQ + m0)) * DMODEL + h * DHEAD + n0]) = v0;
            *reinterpret_cast<float2*>(
                &ctx[((long)(b * SEQ + m0 + 8)) * DMODEL + h * DHEAD + n0]) = v1;
        }
    }
}

// ---------------------------------------------------------------------------
// Host launcher
// ---------------------------------------------------------------------------
extern "C" void kernel_launch(void* const* d_in, const int* in_sizes, int n_in,
                              void* d_out_, int out_size)
{
    const float* q    = (const float*)d_in[0];
    const float* k    = (const float*)d_in[1];
    const float* v    = (const float*)d_in[2];
    const float* wq_w = (const float*)d_in[3];
    const float* wq_b = (const float*)d_in[4];
    const float* wk_w = (const float*)d_in[5];
    const float* wk_b = (const float*)d_in[6];
    const float* wv_w = (const float*)d_in[7];
    const float* wv_b = (const float*)d_in[8];
    const float* wo_w = (const float*)d_in[9];
    const float* wo_b = (const float*)d_in[10];
    float* d_out = (float*)d_out_;

    float *gq, *gk, *gv, *gctx, *gattn;
    { void* p;
      cudaGetSymbolAddress(&p, g_q);    gq    = (float*)p;
      cudaGetSymbolAddress(&p, g_k);    gk    = (float*)p;
      cudaGetSymbolAddress(&p, g_v);    gv    = (float*)p;
      cudaGetSymbolAddress(&p, g_ctx);  gctx  = (float*)p;
      cudaGetSymbolAddress(&p, g_attn); gattn = (float*)p;
    }

    // Output layout handling (reference returns (output, attn_weights))
    float* attnp;
    bool do_output = true;
    if ((long)out_size >= OUT0 + ATTNSZ) {
        attnp = d_out + OUT0;                 // both outputs in d_out
    } else if ((long)out_size >= OUT0) {
        attnp = gattn;                        // only 'output' requested
    } else {
        attnp = d_out;                        // only attn requested
        do_output = false;
    }

    cudaFuncSetAttribute(scores_kernel,
                         cudaFuncAttributeMaxDynamicSharedMemorySize, SC_SMEM_BYTES);

    const dim3 blk(256);

    // 1-3. Q/K/V projections -> head-major
    gemm_proj<1><<<dim3(DMODEL / 128, MROWS / 128), blk>>>(q, wq_w, wq_b, gq, DMODEL, DMODEL);
    gemm_proj<1><<<dim3(DMODEL / 128, MROWS / 128), blk>>>(k, wk_w, wk_b, gk, DMODEL, DMODEL);
    gemm_proj<1><<<dim3(DMODEL / 128, MROWS / 128), blk>>>(v, wv_w, wv_b, gv, DMODEL, DMODEL);

    // 4. Raw scores (single-K-shot tf32 GEMM, streaming stores)
    scores_kernel<<<dim3(SEQ / 128, SEQ / 128, BATCH * NHEAD), blk, SC_SMEM_BYTES>>>(
        gq, gk, attnp);

    // 5+6. Fused softmax (writes normalized attn) + context GEMM
    softmax_context<<<dim3(SEQ / 128, BATCH * NHEAD), blk>>>(attnp, gv, gctx);

    // 7. Output projection
    if (do_output) {
        gemm_proj<0><<<dim3(DMODEL / 128, MROWS / 128), blk>>>(
            gctx, wo_w, wo_b, d_out, DMODEL, DMODEL);
    }
}

// round 14
// speedup vs baseline: 2.7259x; 1.1160x over previous
#include <cuda_runtime.h>

// Problem constants (fixed by the reference)
#define BATCH   2
#define SEQ     2048
#define DMODEL  768
#define NHEAD   12
#define DHEAD   64
#define MROWS   (BATCH * SEQ)                      // 4096
#define OUT0    ((long)MROWS * DMODEL)             // 3,145,728
#define ATTNSZ  ((long)BATCH * NHEAD * SEQ * SEQ)  // 100,663,296
#define NROWS   (BATCH * NHEAD * SEQ)              // 49152 attn rows
#define NTILES  16                                 // 128-col tiles per row

// ---------------------------------------------------------------------------
// Scratch (static __device__ arrays: allocation-free per harness rules)
// ---------------------------------------------------------------------------
__device__ float  g_q[BATCH * NHEAD * SEQ * DHEAD];
__device__ float  g_k[BATCH * NHEAD * SEQ * DHEAD];
__device__ float  g_v[BATCH * NHEAD * SEQ * DHEAD];
__device__ float  g_ctx[MROWS * DMODEL];
__device__ float  g_attn[BATCH * NHEAD * SEQ * SEQ];   // fallback attn buffer
__device__ float2 g_part[(long)NROWS * NTILES];        // partial (max, expsum)
__device__ float2 g_stats[NROWS];                      // final (max, 1/sum)

__device__ __forceinline__ unsigned f2tf32(float f) {
    unsigned u;
    asm("cvt.rna.tf32.f32 %0, %1;" : "=r"(u) : "f"(f));
    return u;
}

__device__ __forceinline__ void mma_tf32(float c[4], const unsigned a[4], const unsigned b[2]) {
    asm volatile(
        "mma.sync.aligned.m16n8k8.row.col.f32.tf32.tf32.f32 "
        "{%0,%1,%2,%3}, {%4,%5,%6,%7}, {%8,%9}, {%0,%1,%2,%3};\n"
        : "+f"(c[0]), "+f"(c[1]), "+f"(c[2]), "+f"(c[3])
        : "r"(a[0]), "r"(a[1]), "r"(a[2]), "r"(a[3]), "r"(b[0]), "r"(b[1]));
}

__device__ __forceinline__ uint4 cvt4(float4 v) {
    uint4 u;
    u.x = f2tf32(v.x); u.y = f2tf32(v.y); u.z = f2tf32(v.z); u.w = f2tf32(v.w);
    return u;
}

// ===========================================================================
// Projection / output GEMM (NT):  C[m,n] = sum_k A[m,k]*B[n,k] + bias[n]
// BM=BN=128, BK=32, 256 thr, warp tile 64x32, K-contiguous smem, prefetch.
// MODE 1: head-major write. MODE 0: row-major.
// ===========================================================================
template<int MODE>
__global__ __launch_bounds__(256)
void gemm_proj(const float* __restrict__ A, const float* __restrict__ B,
               const float* __restrict__ bias, float* __restrict__ C,
               int N, int K)
{
    constexpr int BK = 32;
    __shared__ unsigned As[128][BK + 4];
    __shared__ unsigned Bs[128][BK + 4];

    const int bm = blockIdx.y * 128;
    const int bn = blockIdx.x * 128;
    const int t = threadIdx.x, warp = t >> 5, lane = t & 31;
    const int g = lane >> 2, tig = lane & 3;
    const int wm = (warp >> 2) * 64;
    const int wn = (warp & 3) * 32;

    const int lrow = t >> 3;
    const int lk   = (t & 7) * 4;

    float acc[4][4][4];
    #pragma unroll
    for (int i = 0; i < 4; i++)
        #pragma unroll
        for (int j = 0; j < 4; j++)
            #pragma unroll
            for (int r = 0; r < 4; r++) acc[i][j][r] = 0.0f;

    float4 a4[4], b4[4];
    #pragma unroll
    for (int r = 0; r < 4; r++) {
        a4[r] = *reinterpret_cast<const float4*>(&A[(long)(bm + lrow + 32 * r) * K + lk]);
        b4[r] = *reinterpret_cast<const float4*>(&B[(long)(bn + lrow + 32 * r) * K + lk]);
    }

    for (int k0 = 0; k0 < K; k0 += BK) {
        __syncthreads();
        #pragma unroll
        for (int r = 0; r < 4; r++) {
            *reinterpret_cast<uint4*>(&As[lrow + 32 * r][lk]) = cvt4(a4[r]);
            *reinterpret_cast<uint4*>(&Bs[lrow + 32 * r][lk]) = cvt4(b4[r]);
        }
        __syncthreads();
        if (k0 + BK < K) {
            #pragma unroll
            for (int r = 0; r < 4; r++) {
                a4[r] = *reinterpret_cast<const float4*>(
                    &A[(long)(bm + lrow + 32 * r) * K + k0 + BK + lk]);
                b4[r] = *reinterpret_cast<const float4*>(
                    &B[(long)(bn + lrow + 32 * r) * K + k0 + BK + lk]);
            }
        }

        #pragma unroll
        for (int ks = 0; ks < BK / 8; ks++) {
            const int kk = ks * 8;
            unsigned af[4][4], bf[4][2];
            #pragma unroll
            for (int mi = 0; mi < 4; mi++) {
                const int mrow = wm + mi * 16 + g;
                af[mi][0] = As[mrow    ][kk + tig    ];
                af[mi][1] = As[mrow + 8][kk + tig    ];
                af[mi][2] = As[mrow    ][kk + tig + 4];
                af[mi][3] = As[mrow + 8][kk + tig + 4];
            }
            #pragma unroll
            for (int nj = 0; nj < 4; nj++) {
                const int ncol = wn + nj * 8 + g;
                bf[nj][0] = Bs[ncol][kk + tig    ];
                bf[nj][1] = Bs[ncol][kk + tig + 4];
            }
            #pragma unroll
            for (int mi = 0; mi < 4; mi++)
                #pragma unroll
                for (int nj = 0; nj < 4; nj++)
                    mma_tf32(acc[mi][nj], af[mi], bf[nj]);
        }
    }

    #pragma unroll
    for (int mi = 0; mi < 4; mi++) {
        #pragma unroll
        for (int nj = 0; nj < 4; nj++) {
            const int m0 = bm + wm + mi * 16 + g;
            const int n0 = bn + wn + nj * 8 + tig * 2;
            const float bv0 = bias[n0], bv1 = bias[n0 + 1];
            float2 v0, v1;
            v0.x = acc[mi][nj][0] + bv0; v0.y = acc[mi][nj][1] + bv1;
            v1.x = acc[mi][nj][2] + bv0; v1.y = acc[mi][nj][3] + bv1;
            if (MODE == 1) {
                const int h = n0 >> 6, d = n0 & 63;
                const int b0i = m0 >> 11,       s0 = m0 & 2047;
                const int b1i = (m0 + 8) >> 11, s1 = (m0 + 8) & 2047;
                *reinterpret_cast<float2*>(
                    &C[((long)(b0i * NHEAD + h) * SEQ + s0) * DHEAD + d]) = v0;
                *reinterpret_cast<float2*>(
                    &C[((long)(b1i * NHEAD + h) * SEQ + s1) * DHEAD + d]) = v1;
            } else {
                *reinterpret_cast<float2*>(&C[(long)m0 * N + n0]) = v0;
                *reinterpret_cast<float2*>(&C[(long)(m0 + 8) * N + n0]) = v1;
            }
        }
    }
}

// ===========================================================================
// Pass 1: scores + partial softmax stats. NO gmem score write.
// 128x128 tile, single BK=64 shot. Emits per-(row, col-tile) (max, expsum).
// ===========================================================================
#define SC_SMEM_BYTES (2 * 128 * 68 * 4)

__global__ __launch_bounds__(256)
void scores_stats(const float* __restrict__ Q, const float* __restrict__ Km,
                  float2* __restrict__ part)
{
    extern __shared__ unsigned sm[];
    unsigned (*As)[68] = reinterpret_cast<unsigned(*)[68]>(sm);
    unsigned (*Bs)[68] = reinterpret_cast<unsigned(*)[68]>(sm + 128 * 68);
    __shared__ float2 spart[128][4];

    const int bh = blockIdx.z;
    const int bm = blockIdx.y * 128;
    const int bn = blockIdx.x * 128;
    const float* A = Q  + (long)bh * SEQ * DHEAD;
    const float* B = Km + (long)bh * SEQ * DHEAD;

    const int t = threadIdx.x, warp = t >> 5, lane = t & 31;
    const int g = lane >> 2, tig = lane & 3;
    const int wm = (warp >> 2) * 64;
    const int wn = (warp & 3) * 32;
    (void)wn;

    const int lrow = t >> 4;
    const int lk   = (t & 15) * 4;

    float4 a4[8], b4[8];
    #pragma unroll
    for (int r = 0; r < 8; r++) {
        a4[r] = *reinterpret_cast<const float4*>(&A[(long)(bm + lrow + 16 * r) * DHEAD + lk]);
        b4[r] = *reinterpret_cast<const float4*>(&B[(long)(bn + lrow + 16 * r) * DHEAD + lk]);
    }
    #pragma unroll
    for (int r = 0; r < 8; r++) {
        *reinterpret_cast<uint4*>(&As[lrow + 16 * r][lk]) = cvt4(a4[r]);
        *reinterpret_cast<uint4*>(&Bs[lrow + 16 * r][lk]) = cvt4(b4[r]);
    }
    __syncthreads();

    float acc[4][4][4];
    #pragma unroll
    for (int i = 0; i < 4; i++)
        #pragma unroll
        for (int j = 0; j < 4; j++)
            #pragma unroll
            for (int r = 0; r < 4; r++) acc[i][j][r] = 0.0f;

    #pragma unroll
    for (int ks = 0; ks < 8; ks++) {
        const int kk = ks * 8;
        unsigned af[4][4], bf[4][2];
        #pragma unroll
        for (int mi = 0; mi < 4; mi++) {
            const int mrow = wm + mi * 16 + g;
            af[mi][0] = As[mrow    ][kk + tig    ];
            af[mi][1] = As[mrow + 8][kk + tig    ];
            af[mi][2] = As[mrow    ][kk + tig + 4];
            af[mi][3] = As[mrow + 8][kk + tig + 4];
        }
        #pragma unroll
        for (int nj = 0; nj < 4; nj++) {
            const int ncol = ((warp & 3) * 32) + nj * 8 + g;
            bf[nj][0] = Bs[ncol][kk + tig    ];
            bf[nj][1] = Bs[ncol][kk + tig + 4];
        }
        #pragma unroll
        for (int mi = 0; mi < 4; mi++)
            #pragma unroll
            for (int nj = 0; nj < 4; nj++)
                mma_tf32(acc[mi][nj], af[mi], bf[nj]);
    }

    // Per-row partial stats over this block's 128-col slice (scaled by 1/8).
    #pragma unroll
    for (int mi = 0; mi < 4; mi++) {
        float v0[8], v1[8];
        #pragma unroll
        for (int nj = 0; nj < 4; nj++) {
            v0[nj * 2]     = acc[mi][nj][0] * 0.125f;
            v0[nj * 2 + 1] = acc[mi][nj][1] * 0.125f;
            v1[nj * 2]     = acc[mi][nj][2] * 0.125f;
            v1[nj * 2 + 1] = acc[mi][nj][3] * 0.125f;
        }
        float mx0 = v0[0], mx1 = v1[0];
        #pragma unroll
        for (int i = 1; i < 8; i++) { mx0 = fmaxf(mx0, v0[i]); mx1 = fmaxf(mx1, v1[i]); }
        mx0 = fmaxf(mx0, __shfl_xor_sync(0xFFFFFFFFu, mx0, 1));
        mx0 = fmaxf(mx0, __shfl_xor_sync(0xFFFFFFFFu, mx0, 2));
        mx1 = fmaxf(mx1, __shfl_xor_sync(0xFFFFFFFFu, mx1, 1));
        mx1 = fmaxf(mx1, __shfl_xor_sync(0xFFFFFFFFu, mx1, 2));
        float s0 = 0.0f, s1 = 0.0f;
        #pragma unroll
        for (int i = 0; i < 8; i++) { s0 += __expf(v0[i] - mx0); s1 += __expf(v1[i] - mx1); }
        s0 += __shfl_xor_sync(0xFFFFFFFFu, s0, 1);
        s0 += __shfl_xor_sync(0xFFFFFFFFu, s0, 2);
        s1 += __shfl_xor_sync(0xFFFFFFFFu, s1, 1);
        s1 += __shfl_xor_sync(0xFFFFFFFFu, s1, 2);
        if (tig == 0) {
            spart[wm + mi * 16 + g    ][warp & 3] = make_float2(mx0, s0);
            spart[wm + mi * 16 + g + 8][warp & 3] = make_float2(mx1, s1);
        }
    }
    __syncthreads();
    if (t < 128) {
        float2 p0 = spart[t][0], p1 = spart[t][1], p2 = spart[t][2], p3 = spart[t][3];
        float M = fmaxf(fmaxf(p0.x, p1.x), fmaxf(p2.x, p3.x));
        float L = p0.y * __expf(p0.x - M) + p1.y * __expf(p1.x - M)
                + p2.y * __expf(p2.x - M) + p3.y * __expf(p3.x - M);
        part[((long)(bh * SEQ + bm + t)) * NTILES + blockIdx.x] = make_float2(M, L);
    }
}

// ===========================================================================
// Combine partial stats -> per-row (max, 1/sum)
// ===========================================================================
__global__ __launch_bounds__(256)
void stats_combine(const float2* __restrict__ part, float2* __restrict__ stats)
{
    const int r = blockIdx.x * 256 + threadIdx.x;
    if (r >= NROWS) return;
    const float2* p = part + (long)r * NTILES;
    float M = p[0].x;
    #pragma unroll
    for (int i = 1; i < NTILES; i++) M = fmaxf(M, p[i].x);
    float L = 0.0f;
    #pragma unroll
    for (int i = 0; i < NTILES; i++) L += p[i].y * __expf(p[i].x - M);
    stats[r] = make_float2(M, 1.0f / L);
}

// ===========================================================================
// Pass 2: recompute scores, normalize with final stats, write attn once,
// and accumulate context = P @ V.  One block = 128 query rows of one (b,h).
// 8 warps: 4 in M (32 rows) x 2 in N; K-tile = 64 keys, 32 tiles.
// smem: Qs[128][68] | Ks[64][68] | Ps[128][68] | Vs[64][72]
// ===========================================================================
#define AC_SMEM_BYTES ((128 * 68 + 64 * 68 + 128 * 68 + 64 * 72) * 4)

__global__ __launch_bounds__(256, 2)
void attn_ctx(const float* __restrict__ Q, const float* __restrict__ Km,
              const float* __restrict__ V, const float2* __restrict__ stats,
              float* __restrict__ attn, float* __restrict__ ctx)
{
    extern __shared__ unsigned dsm[];
    unsigned* Qs = dsm;                          // [128][68]
    unsigned* Ks = dsm + 128 * 68;               // [64][68]
    unsigned* Ps = dsm + 128 * 68 + 64 * 68;     // [128][68]
    unsigned* Vs = dsm + 2 * 128 * 68 + 64 * 68; // [64][72]
    __shared__ float s_m[128], s_inv[128];

    const int bh = blockIdx.y;
    const int b = bh / NHEAD, h = bh % NHEAD;
    const int bm = blockIdx.x * 128;
    const float* Qb = Q  + (long)bh * SEQ * DHEAD;
    const float* Kb = Km + (long)bh * SEQ * DHEAD;
    const float* Vb = V  + (long)bh * SEQ * DHEAD;
    float* attnb = attn + (long)bh * SEQ * SEQ + (long)bm * SEQ;

    const int t = threadIdx.x, warp = t >> 5, lane = t & 31;
    const int g = lane >> 2, tig = lane & 3;
    const int wmS = (warp >> 1) * 32;   // 4 warps in M: rows
    const int wnS = (warp & 1) * 32;    // 2 warps in N: key cols / d cols

    if (t < 128) {
        float2 s = stats[(long)bh * SEQ + bm + t];
        s_m[t] = s.x; s_inv[t] = s.y;
    }

    // Load Q tile (persistent)
    {
        const int lrow = t >> 4, lk = (t & 15) * 4;
        #pragma unroll
        for (int r = 0; r < 8; r++) {
            float4 q4 = *reinterpret_cast<const float4*>(
                &Qb[(long)(bm + lrow + 16 * r) * DHEAD + lk]);
            *reinterpret_cast<uint4*>(&Qs[(lrow + 16 * r) * 68 + lk]) = cvt4(q4);
        }
    }

    float cacc[2][4][4];
    #pragma unroll
    for (int i = 0; i < 2; i++)
        #pragma unroll
        for (int j = 0; j < 4; j++)
            #pragma unroll
            for (int r = 0; r < 4; r++) cacc[i][j][r] = 0.0f;

    const int krow = t >> 4;          // 0..15
    const int kcol = (t & 15) * 4;    // 0..60
    float4 kp[4], vp[4];
    #pragma unroll
    for (int r = 0; r < 4; r++) {
        kp[r] = *reinterpret_cast<const float4*>(&Kb[(long)(krow + 16 * r) * DHEAD + kcol]);
        vp[r] = *reinterpret_cast<const float4*>(&Vb[(long)(krow + 16 * r) * DHEAD + kcol]);
    }

    for (int kt = 0; kt < SEQ / 64; kt++) {
        __syncthreads();   // prev ctx MMA done; Ks/Vs free
        #pragma unroll
        for (int r = 0; r < 4; r++) {
            *reinterpret_cast<uint4*>(&Ks[(krow + 16 * r) * 68 + kcol]) = cvt4(kp[r]);
            *reinterpret_cast<uint4*>(&Vs[(krow + 16 * r) * 72 + kcol]) = cvt4(vp[r]);
        }
        __syncthreads();
        if (kt + 1 < SEQ / 64) {
            const long base = (long)((kt + 1) * 64 + krow) * DHEAD + kcol;
            #pragma unroll
            for (int r = 0; r < 4; r++) {
                kp[r] = *reinterpret_cast<const float4*>(&Kb[base + (long)(16 * r) * DHEAD]);
                vp[r] = *reinterpret_cast<const float4*>(&Vb[base + (long)(16 * r) * DHEAD]);
            }
        }

        // --- S = Q . K^T (recompute, bit-identical k-order to pass 1) ---
        float sacc[2][4][4];
        #pragma unroll
        for (int i = 0; i < 2; i++)
            #pragma unroll
            for (int j = 0; j < 4; j++)
                #pragma unroll
                for (int r = 0; r < 4; r++) sacc[i][j][r] = 0.0f;

        #pragma unroll
        for (int ks = 0; ks < 8; ks++) {
            const int kk = ks * 8;
            unsigned af[2][4], bf[4][2];
            #pragma unroll
            for (int mi = 0; mi < 2; mi++) {
                const int mrow = wmS + mi * 16 + g;
                af[mi][0] = Qs[(mrow    ) * 68 + kk + tig    ];
                af[mi][1] = Qs[(mrow + 8) * 68 + kk + tig    ];
                af[mi][2] = Qs[(mrow    ) * 68 + kk + tig + 4];
                af[mi][3] = Qs[(mrow + 8) * 68 + kk + tig + 4];
            }
            #pragma unroll
            for (int nj = 0; nj < 4; nj++) {
                const int ncol = wnS + nj * 8 + g;
                bf[nj][0] = Ks[ncol * 68 + kk + tig    ];
                bf[nj][1] = Ks[ncol * 68 + kk + tig + 4];
            }
            #pragma unroll
            for (int mi = 0; mi < 2; mi++)
                #pragma unroll
                for (int nj = 0; nj < 4; nj++)
                    mma_tf32(sacc[mi][nj], af[mi], bf[nj]);
        }

        // --- normalize, write attn, stage P in smem ---
        #pragma unroll
        for (int mi = 0; mi < 2; mi++) {
            const int r0 = wmS + mi * 16 + g;
            const int r1 = r0 + 8;
            const float m0 = s_m[r0], i0 = s_inv[r0];
            const float m1 = s_m[r1], i1 = s_inv[r1];
            #pragma unroll
            for (int nj = 0; nj < 4; nj++) {
                const int c = wnS + nj * 8 + tig * 2;   // tile-local col
                float2 q0, q1;
                q0.x = __expf(sacc[mi][nj][0] * 0.125f - m0) * i0;
                q0.y = __expf(sacc[mi][nj][1] * 0.125f - m0) * i0;
                q1.x = __expf(sacc[mi][nj][2] * 0.125f - m1) * i1;
                q1.y = __expf(sacc[mi][nj][3] * 0.125f - m1) * i1;
                __stcs(reinterpret_cast<float2*>(&attnb[(long)r0 * SEQ + kt * 64 + c]), q0);
                __stcs(reinterpret_cast<float2*>(&attnb[(long)r1 * SEQ + kt * 64 + c]), q1);
                uint2 u0, u1;
                u0.x = f2tf32(q0.x); u0.y = f2tf32(q0.y);
                u1.x = f2tf32(q1.x); u1.y = f2tf32(q1.y);
                *reinterpret_cast<uint2*>(&Ps[r0 * 68 + c]) = u0;
                *reinterpret_cast<uint2*>(&Ps[r1 * 68 + c]) = u1;
            }
        }
        __syncthreads();

        // --- ctx += P . V  (B fragments transposed from Vs[key][d]) ---
        #pragma unroll
        for (int ks = 0; ks < 8; ks++) {
            const int kk = ks * 8;
            unsigned af[2][4], bf[4][2];
            #pragma unroll
            for (int mi = 0; mi < 2; mi++) {
                const int mrow = wmS + mi * 16 + g;
                af[mi][0] = Ps[(mrow    ) * 68 + kk + tig    ];
                af[mi][1] = Ps[(mrow + 8) * 68 + kk + tig    ];
                af[mi][2] = Ps[(mrow    ) * 68 + kk + tig + 4];
                af[mi][3] = Ps[(mrow + 8) * 68 + kk + tig + 4];
            }
            #pragma unroll
            for (int nj = 0; nj < 4; nj++) {
                const int dcol = wnS + nj * 8 + g;
                bf[nj][0] = Vs[(kk + tig    ) * 72 + dcol];
                bf[nj][1] = Vs[(kk + tig + 4) * 72 + dcol];
            }
            #pragma unroll
            for (int mi = 0; mi < 2; mi++)
                #pragma unroll
                for (int nj = 0; nj < 4; nj++)
                    mma_tf32(cacc[mi][nj], af[mi], bf[nj]);
        }
    }

    // --- ctx epilogue: merged [B,S,768] ---
    #pragma unroll
    for (int mi = 0; mi < 2; mi++) {
        #pragma unroll
        for (int nj = 0; nj < 4; nj++) {
            const int m0 = bm + wmS + mi * 16 + g;
            const int n0 = wnS + nj * 8 + tig * 2;
            float2 v0, v1;
            v0.x = cacc[mi][nj][0]; v0.y = cacc[mi][nj][1];
            v1.x = cacc[mi][nj][2]; v1.y = cacc[mi][nj][3];
            *reinterpret_cast<float2*>(
                &ctx[((long)(b * SEQ + m0)) * DMODEL + h * DHEAD + n0]) = v0;
            *reinterpret_cast<float2*>(
                &ctx[((long)(b * SEQ + m0 + 8)) * DMODEL + h * DHEAD + n0]) = v1;
        }
    }
}

// ---------------------------------------------------------------------------
// Host launcher
// ---------------------------------------------------------------------------
extern "C" void kernel_launch(void* const* d_in, const int* in_sizes, int n_in,
                              void* d_out_, int out_size)
{
    const float* q    = (const float*)d_in[0];
    const float* k    = (const float*)d_in[1];
    const float* v    = (const float*)d_in[2];
    const float* wq_w = (const float*)d_in[3];
    const float* wq_b = (const float*)d_in[4];
    const float* wk_w = (const float*)d_in[5];
    const float* wk_b = (const float*)d_in[6];
    const float* wv_w = (const float*)d_in[7];
    const float* wv_b = (const float*)d_in[8];
    const float* wo_w = (const float*)d_in[9];
    const float* wo_b = (const float*)d_in[10];
    float* d_out = (float*)d_out_;

    float *gq, *gk, *gv, *gctx, *gattn;
    float2 *gpart, *gstats;
    { void* p;
      cudaGetSymbolAddress(&p, g_q);     gq     = (float*)p;
      cudaGetSymbolAddress(&p, g_k);     gk     = (float*)p;
      cudaGetSymbolAddress(&p, g_v);     gv     = (float*)p;
      cudaGetSymbolAddress(&p, g_ctx);   gctx   = (float*)p;
      cudaGetSymbolAddress(&p, g_attn);  gattn  = (float*)p;
      cudaGetSymbolAddress(&p, g_part);  gpart  = (float2*)p;
      cudaGetSymbolAddress(&p, g_stats); gstats = (float2*)p;
    }

    // Output layout handling (reference returns (output, attn_weights))
    float* attnp;
    bool do_output = true;
    if ((long)out_size >= OUT0 + ATTNSZ) {
        attnp = d_out + OUT0;
    } else if ((long)out_size >= OUT0) {
        attnp = gattn;
    } else {
        attnp = d_out;
        do_output = false;
    }

    cudaFuncSetAttribute(scores_stats,
                         cudaFuncAttributeMaxDynamicSharedMemorySize, SC_SMEM_BYTES);
    cudaFuncSetAttribute(attn_ctx,
                         cudaFuncAttributeMaxDynamicSharedMemorySize, AC_SMEM_BYTES);

    const dim3 blk(256);

    // 1-3. Q/K/V projections -> head-major
    gemm_proj<1><<<dim3(DMODEL / 128, MROWS / 128), blk>>>(q, wq_w, wq_b, gq, DMODEL, DMODEL);
    gemm_proj<1><<<dim3(DMODEL / 128, MROWS / 128), blk>>>(k, wk_w, wk_b, gk, DMODEL, DMODEL);
    gemm_proj<1><<<dim3(DMODEL / 128, MROWS / 128), blk>>>(v, wv_w, wv_b, gv, DMODEL, DMODEL);

    // 4. Pass 1: scores + partial softmax stats (no score write)
    scores_stats<<<dim3(NTILES, SEQ / 128, BATCH * NHEAD), blk, SC_SMEM_BYTES>>>(
        gq, gk, gpart);

    // 5. Combine stats
    stats_combine<<<(NROWS + 255) / 256, 256>>>(gpart, gstats);

    // 6. Pass 2: recompute + normalized attn write + context
    attn_ctx<<<dim3(SEQ / 128, BATCH * NHEAD), blk, AC_SMEM_BYTES>>>(
        gq, gk, gv, gstats, attnp, gctx);

    // 7. Output projection
    if (do_output) {
        gemm_proj<0><<<dim3(DMODEL / 128, MROWS / 128), blk>>>(
            gctx, wo_w, wo_b, d_out, DMODEL, DMODEL);
    }
}